// round 16
// baseline (speedup 1.0000x reference)
#include <cuda_runtime.h>
#include <cuda_fp16.h>
#include <cstdint>

// Fixed dims: D=128, H=4, C=32, OUT=64. N,E from in_sizes.
#define MAXN 50048
#define MAXETOT 850048   // E + N self loops

// ---------------- scratch (device globals; allocation-free) ----------------
__device__ __align__(16) __half g_xlh [(size_t)MAXN * 128];   // projected features (fp16)
__device__ __align__(16) float g_accum[(size_t)MAXN * 128];   // layer output h0 / h1
__device__ __align__(16) float g_as   [(size_t)MAXN * 4];     // layer0 att dots (H=4)
__device__ __align__(16) float g_ad   [(size_t)MAXN * 4];
__device__ __align__(16) float g_as2  [MAXN];                 // layer1 att dots (H=1)
__device__ __align__(16) float g_ad2  [MAXN];
__device__ int g_deg   [MAXN];
__device__ int g_rowptr[MAXN + 1];
__device__ int g_cursor[MAXN];
__device__ int g_csrc  [MAXETOT];

__device__ __forceinline__ float lrelu(float x) { return x > 0.f ? x : 0.2f * x; }

// ================= CSR build (once per call; shared by both layers) =================
__global__ void k_initdeg(int* __restrict__ deg, float* __restrict__ as2,
                          float* __restrict__ ad2, int n) {
    int i = blockIdx.x * blockDim.x + threadIdx.x;
    if (i < n) { deg[i] = 1; as2[i] = 0.f; ad2[i] = 0.f; }   // self loop + zero H1 att
}
__global__ void k_count(const int* __restrict__ dst, int E, int* __restrict__ deg) {
    int e = blockIdx.x * blockDim.x + threadIdx.x;
    if (e < E) atomicAdd(&deg[dst[e]], 1);
}
__global__ void k_scan(const int* __restrict__ deg, int* __restrict__ rowptr,
                       int* __restrict__ cursor, int n) {
    __shared__ int sums[1024];
    int tid = threadIdx.x;                      // 1024 threads
    int chunk = (n + 1023) / 1024;
    int beg = tid * chunk;
    int end = min(beg + chunk, n);
    int s = 0;
    for (int i = beg; i < end; i++) s += deg[i];
    sums[tid] = s;
    __syncthreads();
    for (int off = 1; off < 1024; off <<= 1) {  // Hillis-Steele inclusive scan
        int v = (tid >= off) ? sums[tid - off] : 0;
        __syncthreads();
        sums[tid] += v;
        __syncthreads();
    }
    int run = (tid == 0) ? 0 : sums[tid - 1];
    for (int i = beg; i < end; i++) {
        rowptr[i] = run;
        cursor[i] = run;
        run += deg[i];
    }
    if (end == n) rowptr[n] = run;
}
__global__ void k_fill(const int* __restrict__ src, const int* __restrict__ dst,
                       int E, int Etot, int* __restrict__ cursor, int* __restrict__ csrc) {
    int e = blockIdx.x * blockDim.x + threadIdx.x;
    if (e >= Etot) return;
    int s, d;
    if (e < E) { s = src[e]; d = dst[e]; } else { s = e - E; d = s; }
    int p = atomicAdd(&cursor[d], 1);
    csrc[p] = s;
}

// ================= TF32 tensor-core GEMM (3xTF32) + fused attention epilogue ========
// Block tile 128x64, 8 warps (4x2), warp 32x32.
// If Ch != nullptr: store result as fp16 into Ch (layer GEMMs; bias unused there).
// Else: store fp32 (+bias) into C (projection GEMMs).
// attMode 0: none.  1: H=4 direct store of as/ad.  2: H=1 atomic partials.
__device__ __forceinline__ uint32_t f2tf32(float f) {
    uint32_t r; asm("cvt.rna.tf32.f32 %0, %1;" : "=r"(r) : "f"(f)); return r;
}
__device__ __forceinline__ void mma8(float* d, const uint32_t* a, const uint32_t* b) {
    asm volatile("mma.sync.aligned.m16n8k8.row.col.f32.tf32.tf32.f32 "
        "{%0,%1,%2,%3}, {%4,%5,%6,%7}, {%8,%9}, {%0,%1,%2,%3};"
        : "+f"(d[0]), "+f"(d[1]), "+f"(d[2]), "+f"(d[3])
        : "r"(a[0]), "r"(a[1]), "r"(a[2]), "r"(a[3]), "r"(b[0]), "r"(b[1]));
}

__global__ void __launch_bounds__(256)
k_gemm_mma(const float* __restrict__ A, const float* __restrict__ W,
           const float* __restrict__ bias, float* __restrict__ C,
           __half* __restrict__ Ch, int n, int M,
           const float* __restrict__ attS, const float* __restrict__ attD,
           float* __restrict__ oAs, float* __restrict__ oAd, int attMode) {
    __shared__ __align__(16) float As[128][36];   // stride 36: conflict-free frag loads
    __shared__ __align__(16) float Ws[32][72];    // stride 72: conflict-free frag loads
    const int tid = threadIdx.x, l = tid & 31, wid = tid >> 5;
    const int wr = wid >> 1, wc = wid & 1;        // 4 x 2 warp grid
    const int rowBase = blockIdx.y * 128, colBase = blockIdx.x * 64;
    float acc[2][4][4] = {};                      // [mtile][ntile][frag]

    for (int kt = 0; kt < 128; kt += 32) {
        #pragma unroll
        for (int j = 0; j < 4; j++) {             // stage A chunk [128 x 32]
            int idx = tid + 256 * j;
            int r = idx >> 3, c4 = (idx & 7) * 4;
            float4 v = make_float4(0.f, 0.f, 0.f, 0.f);
            int gr = rowBase + r;
            if (gr < n) v = *(const float4*)&A[(size_t)gr * 128 + kt + c4];
            *(float4*)&As[r][c4] = v;
        }
        #pragma unroll
        for (int j = 0; j < 2; j++) {             // stage W chunk [32 x 64]
            int idx = tid + 256 * j;
            int k = idx >> 4, c4 = (idx & 15) * 4;
            *(float4*)&Ws[k][c4] = *(const float4*)&W[(size_t)(kt + k) * M + colBase + c4];
        }
        __syncthreads();

        #pragma unroll
        for (int k8 = 0; k8 < 4; k8++) {
            const int k0 = k8 * 8;
            uint32_t ahi[2][4], alo[2][4], bhi[4][2], blo[4][2];
            #pragma unroll
            for (int t = 0; t < 2; t++) {
                int r0 = wr * 32 + t * 16 + (l >> 2);
                int c0 = k0 + (l & 3);
                float f[4] = { As[r0][c0], As[r0 + 8][c0],
                               As[r0][c0 + 4], As[r0 + 8][c0 + 4] };
                #pragma unroll
                for (int q = 0; q < 4; q++) {
                    ahi[t][q] = f2tf32(f[q]);
                    alo[t][q] = f2tf32(f[q] - __uint_as_float(ahi[t][q]));
                }
            }
            #pragma unroll
            for (int u = 0; u < 4; u++) {
                int col = wc * 32 + u * 8 + (l >> 2);
                float f0 = Ws[k0 + (l & 3)][col];
                float f1 = Ws[k0 + 4 + (l & 3)][col];
                bhi[u][0] = f2tf32(f0); blo[u][0] = f2tf32(f0 - __uint_as_float(bhi[u][0]));
                bhi[u][1] = f2tf32(f1); blo[u][1] = f2tf32(f1 - __uint_as_float(bhi[u][1]));
            }
            #pragma unroll
            for (int t = 0; t < 2; t++)
                #pragma unroll
                for (int u = 0; u < 4; u++) {
                    mma8(acc[t][u], ahi[t], bhi[u]);
                    mma8(acc[t][u], ahi[t], blo[u]);
                    mma8(acc[t][u], alo[t], bhi[u]);
                }
        }
        __syncthreads();
    }

    // ---- C store (fp16 path for layer GEMMs, fp32 + bias for projections) ----
    #pragma unroll
    for (int t = 0; t < 2; t++) {
        int row0 = rowBase + wr * 32 + t * 16 + (l >> 2);
        #pragma unroll
        for (int u = 0; u < 4; u++) {
            int col0 = colBase + wc * 32 + u * 8 + (l & 3) * 2;   // even
            if (Ch) {
                if (row0 < n)
                    *(__half2*)&Ch[(size_t)row0 * M + col0] =
                        __floats2half2_rn(acc[t][u][0], acc[t][u][1]);
                if (row0 + 8 < n)
                    *(__half2*)&Ch[(size_t)(row0 + 8) * M + col0] =
                        __floats2half2_rn(acc[t][u][2], acc[t][u][3]);
            } else {
                float b0 = 0.f, b1 = 0.f;
                if (bias) { b0 = bias[col0]; b1 = bias[col0 + 1]; }
                if (row0 < n) {
                    C[(size_t)row0 * M + col0]     = acc[t][u][0] + b0;
                    C[(size_t)row0 * M + col0 + 1] = acc[t][u][1] + b1;
                }
                if (row0 + 8 < n) {
                    C[(size_t)(row0 + 8) * M + col0]     = acc[t][u][2] + b0;
                    C[(size_t)(row0 + 8) * M + col0 + 1] = acc[t][u][3] + b1;
                }
            }
        }
    }

    // ---- fused attention dots over this warp's 32-col chunk (fp32 accumulators) ----
    if (attMode != 0) {
        const int head = blockIdx.x * 2 + wc;     // H=4: this chunk IS one head
        #pragma unroll
        for (int t = 0; t < 2; t++) {
            float pS[2] = {0.f, 0.f}, pD[2] = {0.f, 0.f};
            #pragma unroll
            for (int u = 0; u < 4; u++) {
                int cl = u * 8 + (l & 3) * 2;     // col within the 32-col chunk
                int cg = (attMode == 1) ? (head * 32 + cl) : (colBase + wc * 32 + cl);
                float wS0 = attS[cg], wS1 = attS[cg + 1];
                float wD0 = attD[cg], wD1 = attD[cg + 1];
                pS[0] += acc[t][u][0] * wS0 + acc[t][u][1] * wS1;
                pS[1] += acc[t][u][2] * wS0 + acc[t][u][3] * wS1;
                pD[0] += acc[t][u][0] * wD0 + acc[t][u][1] * wD1;
                pD[1] += acc[t][u][2] * wD0 + acc[t][u][3] * wD1;
            }
            #pragma unroll
            for (int off = 1; off <= 2; off <<= 1) {
                pS[0] += __shfl_xor_sync(0xffffffffu, pS[0], off);
                pS[1] += __shfl_xor_sync(0xffffffffu, pS[1], off);
                pD[0] += __shfl_xor_sync(0xffffffffu, pD[0], off);
                pD[1] += __shfl_xor_sync(0xffffffffu, pD[1], off);
            }
            if ((l & 3) == 0) {
                int row0 = rowBase + wr * 32 + t * 16 + (l >> 2);
                if (attMode == 1) {
                    if (row0 < n)     { oAs[row0 * 4 + head] = pS[0];       oAd[row0 * 4 + head] = pD[0]; }
                    if (row0 + 8 < n) { oAs[(row0 + 8) * 4 + head] = pS[1]; oAd[(row0 + 8) * 4 + head] = pD[1]; }
                } else {              // H=1: 4 partials per row across (bx, wc)
                    if (row0 < n)     { atomicAdd(&oAs[row0], pS[0]);     atomicAdd(&oAd[row0], pD[0]); }
                    if (row0 + 8 < n) { atomicAdd(&oAs[row0 + 8], pS[1]); atomicAdd(&oAd[row0 + 8], pD[1]); }
                }
            }
        }
    }
}

// ================= fused GAT aggregation: warp per dst node ========================
// 4 independent online-softmax streams (stride-4) -> 4 L2 gathers in flight / warp.
// xl stored fp16: 256B per edge gather. Exact log-sum-exp merge of the 4 streams.
template <int H>
__global__ void __launch_bounds__(256)
k_agg(const int* __restrict__ rowptr, const int* __restrict__ csrc,
      const float* __restrict__ as_, const float* __restrict__ ad_,
      const __half* __restrict__ xlh, const float* __restrict__ bias,
      float* __restrict__ outh, int n) {
    int d = (blockIdx.x * blockDim.x + threadIdx.x) >> 5;
    if (d >= n) return;
    int l = threadIdx.x & 31;
    const int head = (H == 4) ? (l >> 3) : 0;
    const float a_d = ad_[d * H + head];
    int j = rowptr[d];
    const int end = rowptr[d + 1];

    float m[4]   = {-1e30f, -1e30f, -1e30f, -1e30f};
    float den[4] = {0.f, 0.f, 0.f, 0.f};
    float4 ac[4];
    #pragma unroll
    for (int q = 0; q < 4; q++) ac[q] = make_float4(0.f, 0.f, 0.f, 0.f);

    for (; j + 3 < end; j += 4) {
        int s[4] = { csrc[j], csrc[j + 1], csrc[j + 2], csrc[j + 3] };
        float a[4]; uint2 p[4];
        #pragma unroll
        for (int q = 0; q < 4; q++) {
            a[q] = as_[s[q] * H + head];
            p[q] = *(const uint2*)&xlh[(size_t)s[q] * 128 + l * 4];
        }
        #pragma unroll
        for (int q = 0; q < 4; q++) {
            float av = lrelu(a[q] + a_d);
            float2 f01 = __half22float2(*(const __half2*)&p[q].x);
            float2 f23 = __half22float2(*(const __half2*)&p[q].y);
            float nm = fmaxf(m[q], av);
            float rs = __expf(m[q] - nm), ex = __expf(av - nm);
            den[q] = den[q] * rs + ex;
            ac[q].x = ac[q].x * rs + ex * f01.x;
            ac[q].y = ac[q].y * rs + ex * f01.y;
            ac[q].z = ac[q].z * rs + ex * f23.x;
            ac[q].w = ac[q].w * rs + ex * f23.y;
            m[q] = nm;
        }
    }
    for (; j < end; j++) {       // tail (<=3) into stream 0
        int s0 = csrc[j];
        float av = lrelu(as_[s0 * H + head] + a_d);
        uint2 p0 = *(const uint2*)&xlh[(size_t)s0 * 128 + l * 4];
        float2 f01 = __half22float2(*(const __half2*)&p0.x);
        float2 f23 = __half22float2(*(const __half2*)&p0.y);
        float nm = fmaxf(m[0], av);
        float rs = __expf(m[0] - nm), ex = __expf(av - nm);
        den[0] = den[0] * rs + ex;
        ac[0].x = ac[0].x * rs + ex * f01.x;
        ac[0].y = ac[0].y * rs + ex * f01.y;
        ac[0].z = ac[0].z * rs + ex * f23.x;
        ac[0].w = ac[0].w * rs + ex * f23.y;
        m[0] = nm;
    }

    // exact merge of 4 streams (empty streams contribute exactly 0)
    float mm = fmaxf(fmaxf(m[0], m[1]), fmaxf(m[2], m[3]));
    float dden = 0.f;
    float4 acc = make_float4(0.f, 0.f, 0.f, 0.f);
    #pragma unroll
    for (int q = 0; q < 4; q++) {
        float r = __expf(m[q] - mm);
        dden += den[q] * r;
        acc.x += ac[q].x * r;
        acc.y += ac[q].y * r;
        acc.z += ac[q].z * r;
        acc.w += ac[q].w * r;
    }

    float inv = 1.f / (dden + 1e-16f);
    float4 b = *(const float4*)&bias[l * 4];
    float4 o;
    o.x = fmaxf(acc.x * inv + b.x, 0.f);
    o.y = fmaxf(acc.y * inv + b.y, 0.f);
    o.z = fmaxf(acc.z * inv + b.z, 0.f);
    o.w = fmaxf(acc.w * inv + b.w, 0.f);
    *(float4*)&outh[(size_t)d * 128 + l * 4] = o;
}

// ================= launch (multi-stream DAG, graph-capture-safe fork/join) =========
extern "C" void kernel_launch(void* const* d_in, const int* in_sizes, int n_in,
                              void* d_out, int out_size) {
    const float* x    = (const float*)d_in[0];
    const int*   ei   = (const int*)d_in[1];    // int32 (JAX x64 disabled)
    const float* W0   = (const float*)d_in[2];
    const float* as0w = (const float*)d_in[3];
    const float* ad0w = (const float*)d_in[4];
    const float* b0   = (const float*)d_in[5];
    const float* W1   = (const float*)d_in[6];
    const float* as1w = (const float*)d_in[7];
    const float* ad1w = (const float*)d_in[8];
    const float* b1   = (const float*)d_in[9];
    const float* Wn   = (const float*)d_in[10];
    const float* bn   = (const float*)d_in[11];
    const float* We   = (const float*)d_in[12];
    const float* be   = (const float*)d_in[13];
    float* out = (float*)d_out;

    const int n    = in_sizes[0] / 128;
    const int E    = in_sizes[1] / 2;
    const int Etot = E + n;
    const int* src = ei;
    const int* dst = ei + E;

    float *accum, *as_, *ad_, *as2, *ad2;
    __half* xlh;
    int *deg, *rowptr, *cursor, *csrc;
    cudaGetSymbolAddress((void**)&xlh,    g_xlh);
    cudaGetSymbolAddress((void**)&accum,  g_accum);
    cudaGetSymbolAddress((void**)&as_,    g_as);
    cudaGetSymbolAddress((void**)&ad_,    g_ad);
    cudaGetSymbolAddress((void**)&as2,    g_as2);
    cudaGetSymbolAddress((void**)&ad2,    g_ad2);
    cudaGetSymbolAddress((void**)&deg,    g_deg);
    cudaGetSymbolAddress((void**)&rowptr, g_rowptr);
    cudaGetSymbolAddress((void**)&cursor, g_cursor);
    cudaGetSymbolAddress((void**)&csrc,   g_csrc);

    static cudaStream_t sCSR = nullptr, sEGO = nullptr;
    static cudaEvent_t  evFork = nullptr, evCSR = nullptr, evEGO = nullptr;
    if (!sCSR) {
        cudaStreamCreateWithFlags(&sCSR, cudaStreamNonBlocking);
        cudaStreamCreateWithFlags(&sEGO, cudaStreamNonBlocking);
        cudaEventCreateWithFlags(&evFork, cudaEventDisableTiming);
        cudaEventCreateWithFlags(&evCSR,  cudaEventDisableTiming);
        cudaEventCreateWithFlags(&evEGO,  cudaEventDisableTiming);
    }

    const int T = 256;
    dim3 mmaGrid128(2, (n + 127) / 128);
    dim3 mmaGrid64(1, (n + 127) / 128);
    int nBlocks    = (n + T - 1) / T;
    int eBlocks    = (E + T - 1) / T;
    int etBlocks   = (Etot + T - 1) / T;
    int warpBlocks = (n + 7) / 8;

    // fork side branches off the captured (default) stream
    cudaEventRecord(evFork, 0);
    cudaStreamWaitEvent(sCSR, evFork, 0);
    cudaStreamWaitEvent(sEGO, evFork, 0);

    // ---- branch CSR ----
    k_initdeg<<<nBlocks, T, 0, sCSR>>>(deg, as2, ad2, n);
    k_count<<<eBlocks, T, 0, sCSR>>>(dst, E, deg);
    k_scan<<<1, 1024, 0, sCSR>>>(deg, rowptr, cursor, n);
    k_fill<<<etBlocks, T, 0, sCSR>>>(src, dst, E, Etot, cursor, csrc);
    cudaEventRecord(evCSR, sCSR);

    // ---- branch EGO: h_ego = x @ We + be ----
    k_gemm_mma<<<mmaGrid64, T, 0, sEGO>>>(x, We, be, out, nullptr, n, 64,
                                          nullptr, nullptr, nullptr, nullptr, 0);
    cudaEventRecord(evEGO, sEGO);

    // ---- main chain ----
    k_gemm_mma<<<mmaGrid128, T>>>(x, W0, nullptr, nullptr, xlh, n, 128,
                                  as0w, ad0w, as_, ad_, 1);
    cudaStreamWaitEvent(0, evCSR, 0);                  // join CSR before aggregation
    k_agg<4><<<warpBlocks, T>>>(rowptr, csrc, as_, ad_, xlh, b0, accum, n);   // accum := h0

    k_gemm_mma<<<mmaGrid128, T>>>(accum, W1, nullptr, nullptr, xlh, n, 128,
                                  as1w, ad1w, as2, ad2, 2);
    k_agg<1><<<warpBlocks, T>>>(rowptr, csrc, as2, ad2, xlh, b1, accum, n);   // accum := h1

    k_gemm_mma<<<mmaGrid64, T>>>(accum, Wn, bn, out + (size_t)n * 64, nullptr, n, 64,
                                 nullptr, nullptr, nullptr, nullptr, 0);

    cudaStreamWaitEvent(0, evEGO, 0);                  // join EGO before graph end
}